// round 13
// baseline (speedup 1.0000x reference)
#include <cuda_runtime.h>

// ---------------------------------------------------------------------------
// MaskedBalancedBCELoss — 2-kernel pipeline, speculative threshold split.
//  K1 (one 157 MB streaming read): counts pos/valid; quantizes x=1-p for
//     negatives to top-16 rounded float bits; 7-bin histogram (bins 25..31);
//     MERGED log-product accumulator for positives (+p, full precision) and
//     negatives with f <= 0.125 (bins >= 28, always above threshold);
//     ballot-compacts ONLY bins 25..27 negatives (~2 MB) to u16 scratch.
//  K2: finds T1. Warm (T1 in 25..27): reads the 2 MB scratch; exact
//      log-product for stored bins > T1; 64-sub-bin counts for bin T1.
//      Cold (anything else): full fp32 re-read -> psum exact + 2048-bin count
//      histogram over [0,1) (1/2048 resolution), K1's speculative sum unused.
//      LAST block finalizes (midpoint sub-bin losses) + resets globals.
// ---------------------------------------------------------------------------

#define NB1 7                // bins 25..31
#define NB2 64
#define NCOLD 2048           // cold fine bins over [0,1)
#define BLK 256
#define GRID_CAP 888
#define SCR_ELT (32u << 20)  // u16 elements

__device__ __align__(16) unsigned short g_scr16[SCR_ELT];
__device__ unsigned int g_cnt_blk[GRID_CAP];
__device__ unsigned int g_h1[NB1];
__device__ unsigned int g_h2c[NB2];
__device__ unsigned int g_fcold[NCOLD];
__device__ unsigned int g_pos_cnt;
__device__ unsigned int g_neg_cnt;
__device__ double       g_sum_main;   // K1 merged + K2 warm exact
__device__ double       g_sum_cold;   // cold psum
__device__ unsigned int g_done;

// Cephes-style natural log, pure FMA/ALU (no MUFU). ~1-2 ulp on normals.
__device__ __forceinline__ float fast_log(float x) {
    int   i  = __float_as_int(x);
    int   e  = ((i >> 23) & 0xFF) - 127;
    float m  = __int_as_float((i & 0x007FFFFF) | 0x3F800000);
    if (m > 1.41421356f) { m *= 0.5f; e += 1; }
    float t  = m - 1.0f;
    float z  = t * t;
    float P  = 7.0376836292e-2f;
    P = P * t - 1.1514610310e-1f;
    P = P * t + 1.1676998740e-1f;
    P = P * t - 1.2420140846e-1f;
    P = P * t + 1.4249322787e-1f;
    P = P * t - 1.6668057665e-1f;
    P = P * t + 2.0000714765e-1f;
    P = P * t - 2.4999993993e-1f;
    P = P * t + 3.3333331174e-1f;
    float fe = (float)e;
    float y  = t * z * P;
    y += fe * -2.12194440e-4f;
    y -= 0.5f * z;
    float r  = t + y;
    r += fe * 0.693359375f;
    return r;
}
__device__ __forceinline__ float pos_loss_f(float p) { return fminf(-fast_log(p), 100.0f); }

// Threshold bin from 7-bin hist. 1000 if k==0; -1 if below bin 25; else 25..31.
__device__ __forceinline__ int find_T1(const unsigned* h1, unsigned pos,
                                       long long negtot, long long& k_out) {
    long long k3p = 3LL * (long long)pos;
    long long k = (pos == 0u) ? 0LL : (negtot < k3p ? negtot : k3p);
    k_out = k;
    if (k == 0) return 1000;
    long long c = 0;
    for (int i = NB1 - 1; i >= 0; i--) {
        c += (long long)h1[i];
        if (c >= k) return i + 25;
    }
    return -1;
}

// ---------------------------------------------------------------------------
// K1
// ---------------------------------------------------------------------------
__global__ void __launch_bounds__(BLK, 6) k1_scan(
    const float4* __restrict__ pred4, const float4* __restrict__ gt4,
    const float4* __restrict__ mask4,
    const float* __restrict__ pred, const float* __restrict__ gt,
    const float* __restrict__ mask, int n, int cap, int use_scr)
{
    __shared__ unsigned int sh[2 * BLK];        // u8-packed 7-bin hist (8 slots)
    __shared__ unsigned int s_binsum[8];
    __shared__ unsigned int s_cnt;
    __shared__ unsigned int w_pc[BLK / 32], w_vc[BLK / 32];
    __shared__ float        w_es[BLK / 32];

    const int tid  = threadIdx.x;
    const int lane = tid & 31;
    const unsigned lt = (1u << lane) - 1u;

    sh[tid] = 0u; sh[BLK + tid] = 0u;
    if (tid < 8) s_binsum[tid] = 0u;
    if (tid == 0) s_cnt = 0u;
    __syncthreads();

    unsigned int posc = 0, valc = 0;
    float mAcc = 1.0f;
    int   eAcc = 0;
    const int n4   = n >> 2;
    const int step = gridDim.x * BLK;
    const long long rb = (long long)blockIdx.x * (long long)cap;

    // classify + histogram + merged accumulate; returns store flag (bins 25..27)
    auto procE = [&](float p, float g, float mm, bool in, unsigned short& qout) -> bool {
        bool valid = in && (mm > 0.5f);
        bool ispos = valid && (g > 0.5f);
        valc += valid ? 1u : 0u;
        posc += ispos ? 1u : 0u;
        float xn = 1.0f - p;
        unsigned qq = (__float_as_uint(xn) + 0x8000u) >> 16;   // rounded top-16
        float f = __int_as_float((int)(qq << 16));             // quantized x
        qout = (unsigned short)qq;
        bool isneg = valid && !ispos;
        bool hi  = isneg && (f <= 0.125f);     // bins >= 28
        bool mid = isneg && (f <= 0.21875f);   // bins >= 25
        if (mid) {
            int idx = min((int)((1.0f - f) * 32.0f), 31) - 25;  // 0..6 exact
            sh[(idx >> 2) * BLK + tid] += 1u << ((idx & 3) << 3);
        }
        bool take = ispos || hi;
        float x = ispos ? p : xn;               // full precision value
        float xm = take ? fmaxf(x, 1.1755e-38f) : 1.0f;
        mAcc *= xm;
        int ii = __float_as_int(mAcc);
        eAcc += (ii >> 23) - 127;
        mAcc = __int_as_float((ii & 0x007FFFFF) | 0x3F800000);
        return mid && !hi;                      // store bins 25..27 only
    };

    int ibase = blockIdx.x * BLK;
    while (ibase + step + BLK <= n4) {
        int i0 = ibase + tid, i1 = i0 + step;
        float4 pa = __ldcs(&pred4[i0]), ga = __ldcs(&gt4[i0]), ma = __ldcs(&mask4[i0]);
        float4 pb = __ldcs(&pred4[i1]), gb = __ldcs(&gt4[i1]), mb = __ldcs(&mask4[i1]);
        unsigned short v0, v1, v2, v3, v4, v5, v6, v7;
        bool c0 = procE(pa.x, ga.x, ma.x, true, v0);
        bool c1 = procE(pa.y, ga.y, ma.y, true, v1);
        bool c2 = procE(pa.z, ga.z, ma.z, true, v2);
        bool c3 = procE(pa.w, ga.w, ma.w, true, v3);
        bool c4 = procE(pb.x, gb.x, mb.x, true, v4);
        bool c5 = procE(pb.y, gb.y, mb.y, true, v5);
        bool c6 = procE(pb.z, gb.z, mb.z, true, v6);
        bool c7 = procE(pb.w, gb.w, mb.w, true, v7);
        if (use_scr) {
            unsigned m0 = __ballot_sync(0xffffffffu, c0);
            unsigned m1 = __ballot_sync(0xffffffffu, c1);
            unsigned m2 = __ballot_sync(0xffffffffu, c2);
            unsigned m3 = __ballot_sync(0xffffffffu, c3);
            unsigned m4 = __ballot_sync(0xffffffffu, c4);
            unsigned m5 = __ballot_sync(0xffffffffu, c5);
            unsigned m6 = __ballot_sync(0xffffffffu, c6);
            unsigned m7 = __ballot_sync(0xffffffffu, c7);
            unsigned tot = __popc(m0) + __popc(m1) + __popc(m2) + __popc(m3)
                         + __popc(m4) + __popc(m5) + __popc(m6) + __popc(m7);
            unsigned base = 0;
            if (lane == 0 && tot) base = atomicAdd(&s_cnt, tot);
            base = __shfl_sync(0xffffffffu, base, 0);
            unsigned s = base;
            if (c0) g_scr16[rb + s + __popc(m0 & lt)] = v0; s += __popc(m0);
            if (c1) g_scr16[rb + s + __popc(m1 & lt)] = v1; s += __popc(m1);
            if (c2) g_scr16[rb + s + __popc(m2 & lt)] = v2; s += __popc(m2);
            if (c3) g_scr16[rb + s + __popc(m3 & lt)] = v3; s += __popc(m3);
            if (c4) g_scr16[rb + s + __popc(m4 & lt)] = v4; s += __popc(m4);
            if (c5) g_scr16[rb + s + __popc(m5 & lt)] = v5; s += __popc(m5);
            if (c6) g_scr16[rb + s + __popc(m6 & lt)] = v6; s += __popc(m6);
            if (c7) g_scr16[rb + s + __popc(m7 & lt)] = v7;
        }
        ibase += 2 * step;
    }
    for (; ibase < n4; ibase += step) {
        int i = ibase + tid;
        bool in = i < n4;
        float4 pa = in ? __ldcs(&pred4[i]) : make_float4(0.f, 0.f, 0.f, 0.f);
        float4 ga = in ? __ldcs(&gt4[i])   : make_float4(1.f, 1.f, 1.f, 1.f);
        float4 ma = in ? __ldcs(&mask4[i]) : make_float4(0.f, 0.f, 0.f, 0.f);
        unsigned short v0, v1, v2, v3;
        bool c0 = procE(pa.x, ga.x, ma.x, in, v0);
        bool c1 = procE(pa.y, ga.y, ma.y, in, v1);
        bool c2 = procE(pa.z, ga.z, ma.z, in, v2);
        bool c3 = procE(pa.w, ga.w, ma.w, in, v3);
        if (use_scr) {
            unsigned m0 = __ballot_sync(0xffffffffu, c0);
            unsigned m1 = __ballot_sync(0xffffffffu, c1);
            unsigned m2 = __ballot_sync(0xffffffffu, c2);
            unsigned m3 = __ballot_sync(0xffffffffu, c3);
            unsigned tot = __popc(m0) + __popc(m1) + __popc(m2) + __popc(m3);
            unsigned base = 0;
            if (lane == 0 && tot) base = atomicAdd(&s_cnt, tot);
            base = __shfl_sync(0xffffffffu, base, 0);
            unsigned s = base;
            if (c0) g_scr16[rb + s + __popc(m0 & lt)] = v0; s += __popc(m0);
            if (c1) g_scr16[rb + s + __popc(m1 & lt)] = v1; s += __popc(m1);
            if (c2) g_scr16[rb + s + __popc(m2 & lt)] = v2; s += __popc(m2);
            if (c3) g_scr16[rb + s + __popc(m3 & lt)] = v3;
        }
    }
    if (blockIdx.x == 0) {
        for (int i = (n4 << 2) + tid; i < n; i += BLK) {
            unsigned short q;
            bool st = procE(pred[i], gt[i], mask[i], true, q);
            if (use_scr && st) {
                unsigned o = atomicAdd(&s_cnt, 1u);
                g_scr16[rb + o] = q;
            }
        }
    }
    __syncthreads();

    {   // staggered conflict-free u8 flush: 8 slots x 32 chunks of 8 columns
        const int b     = tid & 7;
        const int chunk = tid >> 3;
        const int w     = (b >> 2) * BLK;
        const int shft  = (b & 3) << 3;
        unsigned s = 0;
#pragma unroll
        for (int jj = 0; jj < 8; jj++) {
            int j = chunk * 8 + ((jj + b) & 7);
            s += (sh[w + j] >> shft) & 0xFFu;
        }
        if (s) atomicAdd(&s_binsum[b], s);
    }

    float esum = -(fast_log(mAcc) + (float)eAcc * 0.69314718056f);
#pragma unroll
    for (int o = 16; o > 0; o >>= 1) {
        posc += __shfl_down_sync(0xffffffffu, posc, o);
        valc += __shfl_down_sync(0xffffffffu, valc, o);
        esum += __shfl_down_sync(0xffffffffu, esum, o);
    }
    if (lane == 0) { w_pc[tid >> 5] = posc; w_vc[tid >> 5] = valc; w_es[tid >> 5] = esum; }
    __syncthreads();

    if (tid < NB1 && s_binsum[tid]) atomicAdd(&g_h1[tid], s_binsum[tid]);
    if (tid == 0) {
        unsigned pc = 0, vc = 0; float es = 0.0f;
#pragma unroll
        for (int w = 0; w < BLK / 32; w++) { pc += w_pc[w]; vc += w_vc[w]; es += w_es[w]; }
        if (pc) atomicAdd(&g_pos_cnt, pc);
        if (vc - pc) atomicAdd(&g_neg_cnt, vc - pc);
        atomicAdd(&g_sum_main, (double)es);
        g_cnt_blk[blockIdx.x] = s_cnt;
    }
}

// ---------------------------------------------------------------------------
// K2: tiny scratch pass (warm) / full re-read (cold) + last-block finalize
// ---------------------------------------------------------------------------
__global__ void __launch_bounds__(BLK) k2_sums(
    const float4* __restrict__ pred4, const float4* __restrict__ gt4,
    const float4* __restrict__ mask4,
    const float* __restrict__ pred, const float* __restrict__ gt,
    const float* __restrict__ mask, int n, int cap, int use_scr,
    float* __restrict__ out)
{
    __shared__ unsigned int s_h1[NB1];
    __shared__ int          s_T1;
    __shared__ unsigned int s_c2[NB2];
    __shared__ unsigned int s_fc[NCOLD];
    __shared__ float        w_es[BLK / 32];
    __shared__ unsigned int s_isLast;

    const int tid = threadIdx.x;
    if (tid < NB1) s_h1[tid] = g_h1[tid];
    if (tid < NB2) s_c2[tid] = 0u;
    __syncthreads();

    if (tid == 0) {
        long long k;
        s_T1 = find_T1(s_h1, g_pos_cnt, (long long)g_neg_cnt, k);
    }
    __syncthreads();
    const int T1 = s_T1;

    const bool warm = use_scr && (T1 >= 25 && T1 <= 27);
    const bool cold = (T1 != 1000) && !warm;

    float mA = 1.0f;
    int   e = 0;
    float esum = 0.0f;

    if (warm) {
        const float xhi = (float)(31 - T1) * 0.03125f;   // above-T1 <=> f <= xhi
        const float xlo = (float)(32 - T1) * 0.03125f;   // in-T1 <=> xhi < f <= xlo
        const int   t1x64 = T1 * 64;
        const long long rb  = (long long)blockIdx.x * (long long)cap;
        const unsigned  cnt = g_cnt_blk[blockIdx.x];
        for (unsigned j = tid; j < cnt; j += BLK) {
            unsigned q = (unsigned)g_scr16[rb + j];
            float f = __int_as_float((int)(q << 16));    // f in (0.125, 0.21875]
            if (f <= xhi) {
                mA *= f;
                int ii = __float_as_int(mA);
                e += (ii >> 23) - 127;
                mA = __int_as_float((ii & 0x007FFFFF) | 0x3F800000);
            } else if (f <= xlo) {
                float p2 = 1.0f - f;                     // exact
                int b2 = max(0, min((int)(p2 * 2048.0f) - t1x64, NB2 - 1));
                atomicAdd(&s_c2[b2], 1u);
            }
        }
        esum = -(fast_log(mA) + (float)e * 0.69314718056f);
    } else if (cold) {
        for (int i = tid; i < NCOLD; i += BLK) s_fc[i] = 0u;
        __syncthreads();
        const int n4 = n >> 2;
        const int stp = gridDim.x * BLK;
        auto hcold = [&](float p, float g, float mm) {
            if (mm > 0.5f) {
                if (g > 0.5f) esum += pos_loss_f(p);
                else {
                    int fb = max(0, min((int)(p * 2048.0f), NCOLD - 1));
                    atomicAdd(&s_fc[fb], 1u);
                }
            }
        };
        for (int ib = blockIdx.x * BLK; ib < n4; ib += stp) {
            int i = ib + tid;
            if (i < n4) {
                float4 p = pred4[i], g = gt4[i], m = mask4[i];
                hcold(p.x, g.x, m.x); hcold(p.y, g.y, m.y);
                hcold(p.z, g.z, m.z); hcold(p.w, g.w, m.w);
            }
        }
        if (blockIdx.x == 0) {
            for (int i = (n4 << 2) + tid; i < n; i += BLK)
                hcold(pred[i], gt[i], mask[i]);
        }
        __syncthreads();
        for (int i = tid; i < NCOLD; i += BLK)
            if (s_fc[i]) atomicAdd(&g_fcold[i], s_fc[i]);
    }

#pragma unroll
    for (int o = 16; o > 0; o >>= 1)
        esum += __shfl_down_sync(0xffffffffu, esum, o);
    if ((tid & 31) == 0) w_es[tid >> 5] = esum;
    __syncthreads();

    if (warm && tid < NB2 && s_c2[tid]) atomicAdd(&g_h2c[tid], s_c2[tid]);
    if (tid == 0) {
        float es = 0.0f;
#pragma unroll
        for (int w = 0; w < BLK / 32; w++) es += w_es[w];
        if (warm)      atomicAdd(&g_sum_main, (double)es);
        else if (cold) atomicAdd(&g_sum_cold, (double)es);
    }

    // ---- last-block finalize ----------------------------------------------
    __threadfence();
    __syncthreads();
    if (tid == 0) {
        unsigned old = atomicAdd(&g_done, 1u);
        s_isLast = (old == gridDim.x - 1u) ? 1u : 0u;
    }
    __syncthreads();
    if (!s_isLast) return;

    if (warm) { if (tid < NB2) s_c2[tid] = g_h2c[tid]; }
    if (cold) { for (int i = tid; i < NCOLD; i += BLK) s_fc[i] = g_fcold[i]; }
    __syncthreads();

    if (tid == 0) {
        unsigned pos = g_pos_cnt;
        long long k;
        int T1f = find_T1(s_h1, pos, (long long)g_neg_cnt, k);
        double denom = (double)pos + (double)k + 1e-6;

        if (k == 0) {
            out[0] = 0.0f;   // pos=0 -> psum=0, nsum=0
        } else if (use_scr && T1f >= 25 && T1f <= 27) {
            auto subloss = [&](int i) -> double {
                float pm = ((float)(T1f * 64 + i) + 0.5f) * (1.0f / 2048.0f);
                return (double)fminf(-fast_log(1.0f - pm), 100.0f);
            };
            long long cAbove1 = 0;
            for (int i = T1f + 1 - 25; i < NB1; i++) cAbove1 += (long long)s_h1[i];
            long long r = k - cAbove1;

            long long c2 = 0, cAbove2 = 0;
            double s2above = 0.0;
            int T2 = -1;
            for (int i = NB2 - 1; i >= 0; i--) {
                long long cn = c2 + (long long)s_c2[i];
                if (cn >= r) { T2 = i; cAbove2 = c2; break; }
                s2above += (double)s_c2[i] * subloss(i);
                c2 = cn;
            }
            double part = 0.0;
            if (T2 >= 0 && s_c2[T2] > 0u) {
                long long r2 = r - cAbove2;
                if (r2 < 0) r2 = 0;
                part = (double)r2 * subloss(T2);
            }
            out[0] = (float)((g_sum_main + s2above + part) / denom);
        } else {
            // cold: psum in g_sum_cold; negatives from 2048-bin midpoints
            auto fineloss = [&](int i) -> double {
                float pm = ((float)i + 0.5f) * (1.0f / 2048.0f);
                return (double)fminf(-fast_log(1.0f - pm), 100.0f);
            };
            long long c2 = 0, cAbove2 = 0;
            double s2above = 0.0;
            int T2 = -1;
            for (int i = NCOLD - 1; i >= 0; i--) {
                long long cn = c2 + (long long)s_fc[i];
                if (cn >= k) { T2 = i; cAbove2 = c2; break; }
                s2above += (double)s_fc[i] * fineloss(i);
                c2 = cn;
            }
            double part = 0.0;
            if (T2 >= 0 && s_fc[T2] > 0u) {
                long long r2 = k - cAbove2;
                if (r2 < 0) r2 = 0;
                part = (double)r2 * fineloss(T2);
            }
            out[0] = (float)((g_sum_cold + s2above + part) / denom);
        }
    }
    __syncthreads();

    // reset globals for graph replay
    if (tid < NB1) g_h1[tid] = 0u;
    if (tid < NB2) g_h2c[tid] = 0u;
    for (int i = tid; i < NCOLD; i += BLK) g_fcold[i] = 0u;
    if (tid == 0) {
        g_pos_cnt  = 0u;
        g_neg_cnt  = 0u;
        g_sum_main = 0.0;
        g_sum_cold = 0.0;
        g_done     = 0u;
    }
}

// ---------------------------------------------------------------------------
extern "C" void kernel_launch(void* const* d_in, const int* in_sizes, int n_in,
                              void* d_out, int out_size)
{
    const float* pred = (const float*)d_in[0];
    const float* gt   = (const float*)d_in[1];
    const float* mask = (const float*)d_in[2];
    float* out = (float*)d_out;
    const int n = in_sizes[0];

    const float4* pred4 = (const float4*)pred;
    const float4* gt4   = (const float4*)gt;
    const float4* mask4 = (const float4*)mask;

    int n4 = n >> 2;
    int grid = (n4 + BLK - 1) / BLK;
    if (grid > GRID_CAP) grid = GRID_CAP;
    if (grid < 1) grid = 1;

    int iters = (n4 + grid * BLK - 1) / (grid * BLK);
    long long cap = (long long)iters * BLK * 4 + 8;   // worst case: all stored
    int use_scr = ((long long)grid * cap <= (long long)SCR_ELT) ? 1 : 0;

    k1_scan<<<grid, BLK>>>(pred4, gt4, mask4, pred, gt, mask, n, (int)cap, use_scr);
    k2_sums<<<grid, BLK>>>(pred4, gt4, mask4, pred, gt, mask, n, (int)cap, use_scr, out);
}

// round 14
// speedup vs baseline: 1.0312x; 1.0312x over previous
#include <cuda_runtime.h>

// ---------------------------------------------------------------------------
// MaskedBalancedBCELoss — 2-kernel pipeline with 16-bit candidate scratch.
//  K1 (one 157 MB streaming read): counts pos/valid in regs; quantizes
//     x = 1-p (neg) / p (pos) to the top-16 rounded float bits (pos tagged by
//     0x8000). Candidacy and the 16-bin histogram are derived from the
//     DEQUANTIZED value, so K2's float-compare classification is bit-exactly
//     consistent with the histogram. Ballot-compacts candidates to u16
//     scratch (~12.5 MB).
//  K2: threshold bin T1 -> one pass over u16 scratch. f = as_float(q<<16) is
//      already the log argument; take-test is ONE compare (f <= xhi; positives
//      have f < 0). Log-sum via 8-way TREE product per uint4 with a single
//      mantissa renorm (ILP-wide, no serial chain). Bin == T1 -> count-only
//      sub-bin shared atomics; finalize uses midpoint losses. Cold fallback:
//      full fp32 re-read with 1024 fine count bins. LAST block (fence+counter)
//      finalizes + resets globals (graph-replay safe).
// ---------------------------------------------------------------------------

#define NB1 16               // bins 16..31 of (int)(p'*32), quantized domain
#define NB2 64
#define NFB 1024             // fine bins over [0,0.5) for the cold fallback
#define BLK 256
#define GRID_CAP 888
#define SCR_ELT (32u << 20)  // 32M u16 elements = 64 MB

__device__ __align__(16) unsigned short g_scr16[SCR_ELT];
__device__ unsigned int g_cnt_blk[GRID_CAP];
__device__ unsigned int g_h1[NB1];
__device__ unsigned int g_h2c[NB2];
__device__ unsigned int g_fc[NFB];
__device__ unsigned int g_pos_cnt;
__device__ unsigned int g_neg_cnt;
__device__ double       g_sum_main;
__device__ unsigned int g_done;

// Cephes-style natural log, pure FMA/ALU (no MUFU). ~1-2 ulp on normals.
__device__ __forceinline__ float fast_log(float x) {
    int   i  = __float_as_int(x);
    int   e  = ((i >> 23) & 0xFF) - 127;
    float m  = __int_as_float((i & 0x007FFFFF) | 0x3F800000);
    if (m > 1.41421356f) { m *= 0.5f; e += 1; }
    float t  = m - 1.0f;
    float z  = t * t;
    float P  = 7.0376836292e-2f;
    P = P * t - 1.1514610310e-1f;
    P = P * t + 1.1676998740e-1f;
    P = P * t - 1.2420140846e-1f;
    P = P * t + 1.4249322787e-1f;
    P = P * t - 1.6668057665e-1f;
    P = P * t + 2.0000714765e-1f;
    P = P * t - 2.4999993993e-1f;
    P = P * t + 3.3333331174e-1f;
    float fe = (float)e;
    float y  = t * z * P;
    y += fe * -2.12194440e-4f;
    y -= 0.5f * z;
    float r  = t + y;
    r += fe * 0.693359375f;
    return r;
}
__device__ __forceinline__ float pos_loss_f(float p) { return fminf(-fast_log(p), 100.0f); }
__device__ __forceinline__ float neg_loss_f(float p) { return fminf(-fast_log(1.0f - p), 100.0f); }

// Threshold bin. 1000 if k==0; -1 if below bin 16 (cold); else T1 in [16,31].
__device__ __forceinline__ int find_T1(const unsigned* h1, unsigned pos,
                                       long long negtot, long long& k_out) {
    long long k3p = 3LL * (long long)pos;
    long long k = (pos == 0u) ? 0LL : (negtot < k3p ? negtot : k3p);
    k_out = k;
    if (k == 0) return 1000;
    long long c = 0;
    for (int i = NB1 - 1; i >= 0; i--) {
        c += (long long)h1[i];
        if (c >= k) return i + 16;
    }
    return -1;
}

// ---------------------------------------------------------------------------
// K1: stream, classify (quantized domain), candidate histogram, compact.
// (identical to the proven R12 kernel)
// ---------------------------------------------------------------------------
__global__ void __launch_bounds__(BLK, 6) k1_scan(
    const float4* __restrict__ pred4, const float4* __restrict__ gt4,
    const float4* __restrict__ mask4,
    const float* __restrict__ pred, const float* __restrict__ gt,
    const float* __restrict__ mask, int n, int cap, int use_scr)
{
    __shared__ unsigned int sh[4 * BLK];
    __shared__ unsigned int s_binsum[NB1];
    __shared__ unsigned int s_cnt;
    __shared__ unsigned int w_pc[BLK / 32], w_vc[BLK / 32];

    const int tid  = threadIdx.x;
    const int lane = tid & 31;
    const unsigned lt = (1u << lane) - 1u;

#pragma unroll
    for (int w = 0; w < 4; w++) sh[w * BLK + tid] = 0u;
    if (tid < NB1) s_binsum[tid] = 0u;
    if (tid == 0) s_cnt = 0u;
    __syncthreads();

    unsigned int posc = 0, valc = 0;
    const int n4   = n >> 2;
    const int step = gridDim.x * BLK;
    const long long rb = (long long)blockIdx.x * (long long)cap;

    auto procE = [&](float p, float g, float mm, bool in, unsigned short& q) -> bool {
        bool valid = in && (mm > 0.5f);
        bool ispos = valid && (g > 0.5f);
        valc += valid ? 1u : 0u;
        posc += ispos ? 1u : 0u;
        float x = ispos ? p : (1.0f - p);
        unsigned qq = (__float_as_uint(x) + 0x8000u) >> 16;  // rounded top-16
        q = (unsigned short)(qq | (ispos ? 0x8000u : 0u));
        float f = __int_as_float((int)(qq << 16));           // quantized x > 0
        bool cand = valid && !ispos && (f <= 0.5f);
        if (cand) {
            int idx = (int)((1.0f - f) * 32.0f) - 16;        // exact; 0..15
            idx = max(0, min(idx, 15));
            sh[(idx >> 2) * BLK + tid] += 1u << ((idx & 3) << 3);
        }
        return ispos || cand;
    };

    int ibase = blockIdx.x * BLK;
    while (ibase + step + BLK <= n4) {
        int i0 = ibase + tid, i1 = i0 + step;
        float4 pa = __ldcs(&pred4[i0]), ga = __ldcs(&gt4[i0]), ma = __ldcs(&mask4[i0]);
        float4 pb = __ldcs(&pred4[i1]), gb = __ldcs(&gt4[i1]), mb = __ldcs(&mask4[i1]);
        unsigned short v0, v1, v2, v3, v4, v5, v6, v7;
        bool c0 = procE(pa.x, ga.x, ma.x, true, v0);
        bool c1 = procE(pa.y, ga.y, ma.y, true, v1);
        bool c2 = procE(pa.z, ga.z, ma.z, true, v2);
        bool c3 = procE(pa.w, ga.w, ma.w, true, v3);
        bool c4 = procE(pb.x, gb.x, mb.x, true, v4);
        bool c5 = procE(pb.y, gb.y, mb.y, true, v5);
        bool c6 = procE(pb.z, gb.z, mb.z, true, v6);
        bool c7 = procE(pb.w, gb.w, mb.w, true, v7);
        if (use_scr) {
            unsigned m0 = __ballot_sync(0xffffffffu, c0);
            unsigned m1 = __ballot_sync(0xffffffffu, c1);
            unsigned m2 = __ballot_sync(0xffffffffu, c2);
            unsigned m3 = __ballot_sync(0xffffffffu, c3);
            unsigned m4 = __ballot_sync(0xffffffffu, c4);
            unsigned m5 = __ballot_sync(0xffffffffu, c5);
            unsigned m6 = __ballot_sync(0xffffffffu, c6);
            unsigned m7 = __ballot_sync(0xffffffffu, c7);
            unsigned tot = __popc(m0) + __popc(m1) + __popc(m2) + __popc(m3)
                         + __popc(m4) + __popc(m5) + __popc(m6) + __popc(m7);
            unsigned base = 0;
            if (lane == 0 && tot) base = atomicAdd(&s_cnt, tot);
            base = __shfl_sync(0xffffffffu, base, 0);
            unsigned s = base;
            if (c0) g_scr16[rb + s + __popc(m0 & lt)] = v0; s += __popc(m0);
            if (c1) g_scr16[rb + s + __popc(m1 & lt)] = v1; s += __popc(m1);
            if (c2) g_scr16[rb + s + __popc(m2 & lt)] = v2; s += __popc(m2);
            if (c3) g_scr16[rb + s + __popc(m3 & lt)] = v3; s += __popc(m3);
            if (c4) g_scr16[rb + s + __popc(m4 & lt)] = v4; s += __popc(m4);
            if (c5) g_scr16[rb + s + __popc(m5 & lt)] = v5; s += __popc(m5);
            if (c6) g_scr16[rb + s + __popc(m6 & lt)] = v6; s += __popc(m6);
            if (c7) g_scr16[rb + s + __popc(m7 & lt)] = v7;
        }
        ibase += 2 * step;
    }
    for (; ibase < n4; ibase += step) {
        int i = ibase + tid;
        bool in = i < n4;
        float4 pa = in ? __ldcs(&pred4[i]) : make_float4(0.f, 0.f, 0.f, 0.f);
        float4 ga = in ? __ldcs(&gt4[i])   : make_float4(1.f, 1.f, 1.f, 1.f);
        float4 ma = in ? __ldcs(&mask4[i]) : make_float4(0.f, 0.f, 0.f, 0.f);
        unsigned short v0, v1, v2, v3;
        bool c0 = procE(pa.x, ga.x, ma.x, in, v0);
        bool c1 = procE(pa.y, ga.y, ma.y, in, v1);
        bool c2 = procE(pa.z, ga.z, ma.z, in, v2);
        bool c3 = procE(pa.w, ga.w, ma.w, in, v3);
        if (use_scr) {
            unsigned m0 = __ballot_sync(0xffffffffu, c0);
            unsigned m1 = __ballot_sync(0xffffffffu, c1);
            unsigned m2 = __ballot_sync(0xffffffffu, c2);
            unsigned m3 = __ballot_sync(0xffffffffu, c3);
            unsigned tot = __popc(m0) + __popc(m1) + __popc(m2) + __popc(m3);
            unsigned base = 0;
            if (lane == 0 && tot) base = atomicAdd(&s_cnt, tot);
            base = __shfl_sync(0xffffffffu, base, 0);
            unsigned s = base;
            if (c0) g_scr16[rb + s + __popc(m0 & lt)] = v0; s += __popc(m0);
            if (c1) g_scr16[rb + s + __popc(m1 & lt)] = v1; s += __popc(m1);
            if (c2) g_scr16[rb + s + __popc(m2 & lt)] = v2; s += __popc(m2);
            if (c3) g_scr16[rb + s + __popc(m3 & lt)] = v3;
        }
    }
    if (blockIdx.x == 0) {
        for (int i = (n4 << 2) + tid; i < n; i += BLK) {
            float p = pred[i], g = gt[i], mm = mask[i];
            bool valid = mm > 0.5f;
            bool ispos = valid && (g > 0.5f);
            if (valid) valc++;
            if (ispos) posc++;
            float x = ispos ? p : (1.0f - p);
            unsigned qq = (__float_as_uint(x) + 0x8000u) >> 16;
            float f = __int_as_float((int)(qq << 16));
            bool cand = valid && !ispos && (f <= 0.5f);
            if (cand) {
                int idx = (int)((1.0f - f) * 32.0f) - 16;
                idx = max(0, min(idx, 15));
                sh[(idx >> 2) * BLK + tid] += 1u << ((idx & 3) << 3);
            }
            if (use_scr && (ispos || cand)) {
                unsigned o = atomicAdd(&s_cnt, 1u);
                g_scr16[rb + o] = (unsigned short)(qq | (ispos ? 0x8000u : 0u));
            }
        }
    }
    __syncthreads();

    {   // staggered conflict-free u8 flush
        const int b     = tid & 15;
        const int chunk = tid >> 4;
        const int w     = (b >> 2) * BLK;
        const int shft  = (b & 3) << 3;
        unsigned s = 0;
#pragma unroll
        for (int jj = 0; jj < 16; jj++) {
            int j = chunk * 16 + ((jj + b) & 15);
            s += (sh[w + j] >> shft) & 0xFFu;
        }
        if (s) atomicAdd(&s_binsum[b], s);
    }

#pragma unroll
    for (int o = 16; o > 0; o >>= 1) {
        posc += __shfl_down_sync(0xffffffffu, posc, o);
        valc += __shfl_down_sync(0xffffffffu, valc, o);
    }
    if (lane == 0) { w_pc[tid >> 5] = posc; w_vc[tid >> 5] = valc; }
    __syncthreads();

    if (tid < NB1 && s_binsum[tid]) atomicAdd(&g_h1[tid], s_binsum[tid]);
    if (tid == 0) {
        unsigned pc = 0, vc = 0;
#pragma unroll
        for (int w = 0; w < BLK / 32; w++) { pc += w_pc[w]; vc += w_vc[w]; }
        if (pc) atomicAdd(&g_pos_cnt, pc);
        if (vc - pc) atomicAdd(&g_neg_cnt, vc - pc);
        g_cnt_blk[blockIdx.x] = s_cnt;
    }
}

// ---------------------------------------------------------------------------
// K2: tree-product u16 scratch pass + count-only sub-bins + finalize
// ---------------------------------------------------------------------------
__global__ void __launch_bounds__(BLK) k2_sums(
    const float4* __restrict__ pred4, const float4* __restrict__ gt4,
    const float4* __restrict__ mask4,
    const float* __restrict__ pred, const float* __restrict__ gt,
    const float* __restrict__ mask, int n, int cap, int use_scr,
    float* __restrict__ out)
{
    __shared__ unsigned int s_h1[NB1];
    __shared__ int          s_T1;
    __shared__ unsigned int s_c2[NB2];
    __shared__ unsigned int s_fc[NFB];
    __shared__ float        w_es[BLK / 32];
    __shared__ unsigned int s_isLast;

    const int tid = threadIdx.x;
    if (tid < NB1) s_h1[tid] = g_h1[tid];
    if (tid < NB2) s_c2[tid] = 0u;
    __syncthreads();

    if (tid == 0) {
        long long k;
        s_T1 = find_T1(s_h1, g_pos_cnt, (long long)g_neg_cnt, k);
    }
    __syncthreads();
    const int T1 = s_T1;

    // x-domain thresholds (exact multiples of 1/32, zero low-16 bits).
    // warm: above-T1 <=> f <= xhi; in-T1 <=> xhi < f <= xlo.
    // k==0 (T1==1000): xhi = -0.0 -> take = (f <= -0.0) = positives only.
    const bool warm = (T1 >= 16 && T1 < 32);
    const float xhi = warm ? (1.0f - (float)(T1 + 1) * 0.03125f) : -0.0f;
    const float xlo = warm ? (1.0f - (float)T1 * 0.03125f)       : -0.0f;
    const int   t1x64 = warm ? T1 * 64 : 0;

    float mA = 1.0f;
    int   e = 0;
    float esum = 0.0f;

    // rare T1-bin handler (count only)
    auto t1bin = [&](float f) {
        if (f > xhi && f <= xlo) {
            float p2 = 1.0f - f;                       // exact
            int b2 = min((int)(p2 * 2048.0f) - t1x64, NB2 - 1);
            b2 = max(b2, 0);
            atomicAdd(&s_c2[b2], 1u);
        }
    };
    // take-masked factor: data guarantees x >= ~1e-4; clamp at 6.1e-5 keeps
    // the 8-way product normal ((6.1e-5)^8 = 1.9e-34 > FLT_MIN) and is inert.
    auto factor = [&](float f) -> float {
        return (f <= xhi) ? fmaxf(fabsf(f), 6.1e-5f) : 1.0f;
    };
    // scalar fallback (tails): per-element renorm
    auto pv1 = [&](unsigned q) {
        float f = __int_as_float((int)(q << 16));
        t1bin(f);
        mA *= factor(f);
        int i = __float_as_int(mA);
        e += (i >> 23) - 127;
        mA = __int_as_float((i & 0x007FFFFF) | 0x3F800000);
    };

    bool wrote_fine = false;

    if (use_scr && T1 >= 16) {
        const long long rb  = (long long)blockIdx.x * (long long)cap;
        const unsigned  cnt = g_cnt_blk[blockIdx.x];
        const uint4*    s8  = (const uint4*)&g_scr16[rb];
        const unsigned  c8  = cnt >> 3;            // 8 elements per uint4
        for (unsigned j = tid; j < c8; j += BLK) {
            uint4 A = s8[j];
            // extract: low halves via <<16 (1 instr), high via mask (1 instr)
            float f0 = __int_as_float((int)(A.x << 16));
            float f1 = __int_as_float((int)(A.x & 0xFFFF0000u));
            float f2 = __int_as_float((int)(A.y << 16));
            float f3 = __int_as_float((int)(A.y & 0xFFFF0000u));
            float f4 = __int_as_float((int)(A.z << 16));
            float f5 = __int_as_float((int)(A.z & 0xFFFF0000u));
            float f6 = __int_as_float((int)(A.w << 16));
            float f7 = __int_as_float((int)(A.w & 0xFFFF0000u));
            t1bin(f0); t1bin(f1); t1bin(f2); t1bin(f3);
            t1bin(f4); t1bin(f5); t1bin(f6); t1bin(f7);
            // 8-way tree product, single renorm
            float t01 = factor(f0) * factor(f1);
            float t23 = factor(f2) * factor(f3);
            float t45 = factor(f4) * factor(f5);
            float t67 = factor(f6) * factor(f7);
            float t03 = t01 * t23;
            float t47 = t45 * t67;
            mA *= t03 * t47;
            int ii = __float_as_int(mA);
            e += (ii >> 23) - 127;
            mA = __int_as_float((ii & 0x007FFFFF) | 0x3F800000);
        }
        for (unsigned t = (c8 << 3) + tid; t < cnt; t += BLK)
            pv1((unsigned)g_scr16[rb + t]);
    } else {
        // cold path: full fp32 re-read (quantization-free)
        wrote_fine = (T1 == -1);
        for (int i = tid; i < NFB; i += BLK) s_fc[i] = 0u;
        __syncthreads();
        const int n4 = n >> 2;
        const int stp = gridDim.x * BLK;
        auto hfull = [&](float p, float g, float mm) {
            if (mm > 0.5f) {
                if (g > 0.5f) { esum += pos_loss_f(p); return; }
                if (T1 == 1000) return;
                if (p >= 0.5f) esum += neg_loss_f(p);
                else {
                    int fb = max(0, min((int)(p * 2048.0f), NFB - 1));
                    atomicAdd(&s_fc[fb], 1u);
                }
            }
        };
        for (int ib = blockIdx.x * BLK; ib < n4; ib += stp) {
            int i = ib + tid;
            if (i < n4) {
                float4 p = pred4[i], g = gt4[i], m = mask4[i];
                hfull(p.x, g.x, m.x); hfull(p.y, g.y, m.y);
                hfull(p.z, g.z, m.z); hfull(p.w, g.w, m.w);
            }
        }
        if (blockIdx.x == 0) {
            for (int i = (n4 << 2) + tid; i < n; i += BLK)
                hfull(pred[i], gt[i], mask[i]);
        }
        __syncthreads();
        if (wrote_fine) {
            for (int i = tid; i < NFB; i += BLK)
                if (s_fc[i]) atomicAdd(&g_fc[i], s_fc[i]);
        }
    }

    esum += -(fast_log(mA) + (float)e * 0.69314718056f);

#pragma unroll
    for (int o = 16; o > 0; o >>= 1)
        esum += __shfl_down_sync(0xffffffffu, esum, o);
    if ((tid & 31) == 0) w_es[tid >> 5] = esum;
    __syncthreads();

    if (tid < NB2 && s_c2[tid]) atomicAdd(&g_h2c[tid], s_c2[tid]);
    if (tid == 0) {
        float es = 0.0f;
#pragma unroll
        for (int w = 0; w < BLK / 32; w++) es += w_es[w];
        atomicAdd(&g_sum_main, (double)es);
    }

    // ---- last-block finalize ----------------------------------------------
    __threadfence();
    __syncthreads();
    if (tid == 0) {
        unsigned old = atomicAdd(&g_done, 1u);
        s_isLast = (old == gridDim.x - 1u) ? 1u : 0u;
    }
    __syncthreads();
    if (!s_isLast) return;

    if (tid < NB2) s_c2[tid] = g_h2c[tid];
    if (T1 == -1) {
        for (int i = tid; i < NFB; i += BLK) s_fc[i] = g_fc[i];
    }
    __syncthreads();

    if (tid == 0) {
        unsigned pos = g_pos_cnt;
        long long k;
        int T1f = find_T1(s_h1, pos, (long long)g_neg_cnt, k);

        double extra = 0.0;
        if (k > 0) {
            if (T1f >= 16 && T1f < 32) {
                auto subloss = [&](int i) -> double {
                    float pm = ((float)(T1f * 64 + i) + 0.5f) * (1.0f / 2048.0f);
                    return (double)fminf(-fast_log(1.0f - pm), 100.0f);
                };
                long long cAbove1 = 0;
                for (int i = T1f + 1 - 16; i < NB1; i++) cAbove1 += (long long)s_h1[i];
                long long r = k - cAbove1;

                long long c2 = 0, cAbove2 = 0;
                double s2above = 0.0;
                int T2 = -1;
                for (int i = NB2 - 1; i >= 0; i--) {
                    long long cn = c2 + (long long)s_c2[i];
                    if (cn >= r) { T2 = i; cAbove2 = c2; break; }
                    s2above += (double)s_c2[i] * subloss(i);
                    c2 = cn;
                }
                double part = 0.0;
                if (T2 >= 0 && s_c2[T2] > 0u) {
                    long long r2 = r - cAbove2;
                    if (r2 < 0) r2 = 0;
                    part = (double)r2 * subloss(T2);
                }
                extra = s2above + part;
            } else if (T1f == -1) {
                auto fineloss = [&](int i) -> double {
                    float pm = ((float)i + 0.5f) * (1.0f / 2048.0f);
                    return (double)fminf(-fast_log(1.0f - pm), 100.0f);
                };
                long long cand = 0;
                for (int i = 0; i < NB1; i++) cand += (long long)s_h1[i];
                long long r = k - cand;
                long long c2 = 0, cAbove2 = 0;
                double s2above = 0.0;
                int T2 = -1;
                for (int i = NFB - 1; i >= 0; i--) {
                    long long cn = c2 + (long long)s_fc[i];
                    if (cn >= r) { T2 = i; cAbove2 = c2; break; }
                    s2above += (double)s_fc[i] * fineloss(i);
                    c2 = cn;
                }
                double part = 0.0;
                if (T2 >= 0 && s_fc[T2] > 0u) {
                    long long r2 = r - cAbove2;
                    if (r2 < 0) r2 = 0;
                    part = (double)r2 * fineloss(T2);
                }
                extra = s2above + part;
            }
        }

        double denom = (double)pos + (double)k + 1e-6;
        out[0] = (float)((g_sum_main + extra) / denom);
    }
    __syncthreads();

    // reset globals for graph replay
    if (tid < NB1) g_h1[tid] = 0u;
    if (tid < NB2) g_h2c[tid] = 0u;
    for (int i = tid; i < NFB; i += BLK) g_fc[i] = 0u;
    if (tid == 0) {
        g_pos_cnt  = 0u;
        g_neg_cnt  = 0u;
        g_sum_main = 0.0;
        g_done     = 0u;
    }
}

// ---------------------------------------------------------------------------
extern "C" void kernel_launch(void* const* d_in, const int* in_sizes, int n_in,
                              void* d_out, int out_size)
{
    const float* pred = (const float*)d_in[0];
    const float* gt   = (const float*)d_in[1];
    const float* mask = (const float*)d_in[2];
    float* out = (float*)d_out;
    const int n = in_sizes[0];

    const float4* pred4 = (const float4*)pred;
    const float4* gt4   = (const float4*)gt;
    const float4* mask4 = (const float4*)mask;

    int n4 = n >> 2;
    int grid = (n4 + BLK - 1) / BLK;
    if (grid > GRID_CAP) grid = GRID_CAP;
    if (grid < 1) grid = 1;

    int iters = (n4 + grid * BLK - 1) / (grid * BLK);
    long long cap = (long long)iters * BLK * 4 + 8;   // elements (mult of 8)
    int use_scr = ((long long)grid * cap <= (long long)SCR_ELT) ? 1 : 0;

    k1_scan<<<grid, BLK>>>(pred4, gt4, mask4, pred, gt, mask, n, (int)cap, use_scr);
    k2_sums<<<grid, BLK>>>(pred4, gt4, mask4, pred, gt, mask, n, (int)cap, use_scr, out);
}